// round 14
// baseline (speedup 1.0000x reference)
#include <cuda_runtime.h>
#include <cuda_fp16.h>

// Problem constants
#define Tn   2048
#define Dn   1024
#define Hn   16
#define HDn  64
#define Bn   2
#define ROWS (Bn * Tn)   // 4096
#define ZHD  (Bn * Hn)   // 32
#define NQKV 3072        // q|k|v fused output width

// ---------------- scratch (static device globals; no allocations) ----------
__device__ __half g_h1 [ROWS * Dn];
__device__ __half g_qkv[ROWS * NQKV];            // [b*T][3072]: q|k|v (q pre-scaled via Wq)
__device__ __half g_vt [ZHD * HDn * Tn];         // V^T per (b,h)
__device__ __half g_att[ROWS * Dn];
__device__ float  g_x2 [ROWS * Dn];
__device__ __half g_h2 [ROWS * Dn];
__device__ __half g_mid[ROWS * 4 * Dn];
__device__ __half g_wqkvT[NQKV * Dn];            // [3072][1024] fused B operand
__device__ __half g_woT [Dn * Dn];
__device__ __half g_w1T [4 * Dn * Dn];           // [4D][D]
__device__ __half g_w2T [4 * Dn * Dn];           // [D][4D]

// ---------------------------------------------------------------------------
__device__ __forceinline__ unsigned smem_u32(const void* p) {
    return (unsigned)__cvta_generic_to_shared(p);
}
__device__ __forceinline__ void cp16(unsigned dst, const void* src) {
    asm volatile("cp.async.cg.shared.global [%0],[%1],16;\n" :: "r"(dst), "l"(src));
}
#define CP_COMMIT()  asm volatile("cp.async.commit_group;" ::: "memory")
#define CP_WAIT(n)   asm volatile("cp.async.wait_group %0;" :: "n"(n) : "memory")

#define MMA_FP16(d, a, b) \
    asm volatile("mma.sync.aligned.m16n8k16.row.col.f32.f16.f16.f32 " \
                 "{%0,%1,%2,%3},{%4,%5,%6,%7},{%8,%9},{%0,%1,%2,%3};\n" \
                 : "+f"((d)[0]), "+f"((d)[1]), "+f"((d)[2]), "+f"((d)[3]) \
                 : "r"((a)[0]), "r"((a)[1]), "r"((a)[2]), "r"((a)[3]), \
                   "r"((b)[0]), "r"((b)[1]))

// Warp-collective fragment load: 4 x m8n8 b16 matrices.
#define LDSM_X4(r0, r1, r2, r3, addr) \
    asm volatile("ldmatrix.sync.aligned.m8n8.x4.shared.b16 {%0,%1,%2,%3},[%4];\n" \
                 : "=r"(r0), "=r"(r1), "=r"(r2), "=r"(r3) : "r"(addr))

__device__ __forceinline__ unsigned pack_h2(float a, float b) {
    __half2 h = __floats2half2_rn(a, b);
    return *reinterpret_cast<unsigned*>(&h);
}

// ---------------------------------------------------------------------------
// transpose fp32 -> fp16 (with scale): in tile [R][C] -> out [C][R], per-z z*sIn.
// ---------------------------------------------------------------------------
__global__ void transpose_f2h(const float* __restrict__ in,
                              __half* __restrict__ outp,
                              int ldin, long long sIn, int ldout, long long sOut,
                              float scale)
{
    __shared__ float t[32][33];
    int z = blockIdx.z;
    in   += (long long)z * sIn;
    outp += (long long)z * sOut;
    int c0 = blockIdx.x * 32, r0 = blockIdx.y * 32;
    int tx = threadIdx.x, ty = threadIdx.y;
#pragma unroll
    for (int i = 0; i < 32; i += 8)
        t[ty + i][tx] = in[(long long)(r0 + ty + i) * ldin + c0 + tx];
    __syncthreads();
#pragma unroll
    for (int i = 0; i < 32; i += 8)
        outp[(long long)(c0 + ty + i) * ldout + r0 + tx] =
            __float2half_rn(t[tx][ty + i] * scale);
}

// transpose fp16 -> fp16: in tile [R][C] -> out [C][R]; z offsets (z/dz)*sIn1+(z%mz)*sIn2.
__global__ void transpose_h(const __half* __restrict__ in,
                            __half* __restrict__ outp,
                            int ldin, long long sIn1, int dz, long long sIn2, int mz,
                            int ldout, long long sOut)
{
    __shared__ __half t[32][34];
    int z = blockIdx.z;
    in   += (long long)(z / dz) * sIn1 + (long long)(z % mz) * sIn2;
    outp += (long long)z * sOut;
    int c0 = blockIdx.x * 32, r0 = blockIdx.y * 32;
    int tx = threadIdx.x, ty = threadIdx.y;
#pragma unroll
    for (int i = 0; i < 32; i += 8)
        t[ty + i][tx] = in[(long long)(r0 + ty + i) * ldin + c0 + tx];
    __syncthreads();
#pragma unroll
    for (int i = 0; i < 32; i += 8)
        outp[(long long)(c0 + ty + i) * ldout + r0 + tx] = t[tx][ty + i];
}

// ---------------------------------------------------------------------------
// gemm_fp16: single-pass FP16 GEMM (fp32 accum), ldmatrix fragment loads.
//   C = A @ B^T (+epi). A fp16 [M,K]; B fp16 [N,K].
//   EPI: 0 -> fp16 C; 1 -> bias+relu -> fp16 C; 2 -> bias+residual -> fp32 C.
// BM=128, BN=256, BK=64, 256 thr; warps 2m x 4n, warp tile 64x64.
// 2-stage cp.async double buffer, XOR-swizzled smem (LDSM-compatible).
// Stage = (128 A-rows + 256 B-rows) * 128 B = 48 KB; 2 stages = 96 KB dynamic.
// ---------------------------------------------------------------------------
template <int EPI>
__launch_bounds__(256, 1)
__global__ void gemm_fp16(const __half* __restrict__ A,
                          const __half* __restrict__ B,
                          float* __restrict__ C,
                          __half* __restrict__ Ch,
                          const float* __restrict__ bias,
                          const float* __restrict__ res,
                          int N, int K, int lda, int ldb, int ldc)
{
    extern __shared__ unsigned sm[];   // stage s: A at s*12288 words, B at +4096 words

    const int m0 = blockIdx.y * 128;
    const int n0 = blockIdx.x * 256;

    const int tid  = threadIdx.x;
    const int lane = tid & 31;
    const int w    = tid >> 5;
    const int wm   = (w & 1) * 64;
    const int wn   = (w >> 1) * 64;
    const int q    = lane >> 2;
    const int kb   = lane & 3;
    const int nk   = K / 64;

    // ldmatrix lane mapping
    const int mi = lane >> 3;          // matrix index group 0..3
    const int ri = lane & 7;           // row within matrix
    const unsigned aRow = wm + (mi & 1) * 8 + ri;   // + mt*16
    const unsigned bRow = wn + (mi >> 1) * 8 + ri;  // + p*16
    const int caA = mi >> 1;           // chunk half for A (k lo/hi)
    const int caB = mi & 1;            // chunk half for B

    // loader: thread handles rows (tid>>3)+32i, 16B chunk tid&7
    const int lrow = tid >> 3;
    const int lg   = tid & 7;
    const unsigned lsw = ((unsigned)(lg * 4)) ^ ((unsigned)((lrow & 7) * 4));

    float acc[4][8][4];
#pragma unroll
    for (int mt = 0; mt < 4; mt++)
#pragma unroll
        for (int nt = 0; nt < 8; nt++)
#pragma unroll
            for (int j = 0; j < 4; j++) acc[mt][nt][j] = 0.f;

    auto load_stage = [&](int st, int kt) {
        unsigned* sb = sm + st * 12288;
        const int k0 = kt * 64;
#pragma unroll
        for (int i = 0; i < 4; i++) {
            int row = lrow + 32 * i;
            unsigned off = row * 32 + lsw;
            cp16(smem_u32(sb + off), A + (long long)(m0 + row) * lda + k0 + lg * 8);
        }
#pragma unroll
        for (int i = 0; i < 8; i++) {
            int row = lrow + 32 * i;
            unsigned off = row * 32 + lsw;
            cp16(smem_u32(sb + 4096 + off), B + (long long)(n0 + row) * ldb + k0 + lg * 8);
        }
        CP_COMMIT();
    };

    load_stage(0, 0);

    const unsigned sbase0 = smem_u32(sm);

    for (int kt = 0; kt < nk; kt++) {
        if (kt + 1 < nk) {
            load_stage((kt + 1) & 1, kt + 1);
            CP_WAIT(1);
        } else {
            CP_WAIT(0);
        }
        __syncthreads();

        const unsigned sA = sbase0 + (kt & 1) * 49152;         // stage A byte base
        const unsigned sB = sA + 16384;                        // stage B byte base
#pragma unroll
        for (int c = 0; c < 4; c++) {              // 4 x k16 chunks
            unsigned a[4][4], b[8][2];
            const unsigned swzA = (unsigned)(((2 * c + caA) ^ ri) << 4);
            const unsigned swzB = (unsigned)(((2 * c + caB) ^ ri) << 4);
#pragma unroll
            for (int mt = 0; mt < 4; mt++) {
                unsigned addr = sA + (aRow + mt * 16) * 128 + swzA;
                LDSM_X4(a[mt][0], a[mt][1], a[mt][2], a[mt][3], addr);
            }
#pragma unroll
            for (int p = 0; p < 4; p++) {
                unsigned addr = sB + (bRow + p * 16) * 128 + swzB;
                LDSM_X4(b[2 * p][0], b[2 * p][1], b[2 * p + 1][0], b[2 * p + 1][1], addr);
            }
#pragma unroll
            for (int mt = 0; mt < 4; mt++)
#pragma unroll
                for (int nt = 0; nt < 8; nt++)
                    MMA_FP16(acc[mt][nt], a[mt], b[nt]);
        }
        __syncthreads();
    }

    // ---- epilogue
#pragma unroll
    for (int mt = 0; mt < 4; mt++)
#pragma unroll
        for (int nt = 0; nt < 8; nt++) {
            const float* a4 = acc[mt][nt];
            const long long r0 = m0 + wm + mt * 16 + q;
            const long long r1 = r0 + 8;
            const int cc = n0 + wn + nt * 8 + kb * 2;
            if (EPI == 0) {
                *reinterpret_cast<unsigned*>(&Ch[r0 * ldc + cc]) = pack_h2(a4[0], a4[1]);
                *reinterpret_cast<unsigned*>(&Ch[r1 * ldc + cc]) = pack_h2(a4[2], a4[3]);
            } else if (EPI == 1) {
                float2 bv = *reinterpret_cast<const float2*>(&bias[cc]);
                *reinterpret_cast<unsigned*>(&Ch[r0 * ldc + cc]) =
                    pack_h2(fmaxf(a4[0] + bv.x, 0.f), fmaxf(a4[1] + bv.y, 0.f));
                *reinterpret_cast<unsigned*>(&Ch[r1 * ldc + cc]) =
                    pack_h2(fmaxf(a4[2] + bv.x, 0.f), fmaxf(a4[3] + bv.y, 0.f));
            } else {
                float2 bv = *reinterpret_cast<const float2*>(&bias[cc]);
                float2 q0 = *reinterpret_cast<const float2*>(&res[r0 * ldc + cc]);
                float2 q1 = *reinterpret_cast<const float2*>(&res[r1 * ldc + cc]);
                *reinterpret_cast<float2*>(&C[r0 * ldc + cc]) =
                    make_float2(a4[0] + bv.x + q0.x, a4[1] + bv.y + q0.y);
                *reinterpret_cast<float2*>(&C[r1 * ldc + cc]) =
                    make_float2(a4[2] + bv.x + q1.x, a4[3] + bv.y + q1.y);
            }
        }
}

// ---------------------------------------------------------------------------
// Flash attention, FP16 operands / fp32 softmax+accum; ldmatrix K/V loads.
// (unchanged from R12 winner)
// ---------------------------------------------------------------------------
__launch_bounds__(256)
__global__ void flash_fp16(const __half* __restrict__ qkv,
                           const __half* __restrict__ vt,
                           __half* __restrict__ att)
{
    __shared__ __align__(16) unsigned s_w[8192];

    const int z  = blockIdx.y;
    const int m0 = blockIdx.x * 128;
    const int tid = threadIdx.x, lane = tid & 31, w = tid >> 5;
    const int q  = lane >> 2;
    const int kb = lane & 3;
    const unsigned qx = (unsigned)(q << 2);

    const int mi = lane >> 3;
    const int ri = lane & 7;
    const unsigned bRow = (unsigned)((mi >> 1) * 8 + ri);
    const int caB = mi & 1;

    const long long bbase = (long long)(z >> 4) * Tn * NQKV;
    const int hcol = (z & 15) * HDn;

    // ---- stage Q (128x64 halfs, swizzled), extract fp16 A-fragments (scalar, once)
    unsigned qf[4][4];
    {
        const __half* Qg = qkv + bbase + (long long)m0 * NQKV + hcol;
#pragma unroll
        for (int i = 0; i < 4; i++) {
            int idx = tid + 256 * i;
            int r = idx >> 3, ch = idx & 7;
            unsigned sw = r * 32 + (((unsigned)(ch * 4)) ^ ((unsigned)((r & 7) * 4)));
            cp16(smem_u32(s_w + sw), Qg + (long long)r * NQKV + ch * 8);
        }
        CP_COMMIT();
        CP_WAIT(0);
        __syncthreads();
        const int ra = w * 16 + q;
#pragma unroll
        for (int c = 0; c < 4; c++) {
            const unsigned g0 = ((unsigned)(c * 8) ^ qx) + kb;
            const unsigned g1 = ((unsigned)(c * 8 + 4) ^ qx) + kb;
            qf[c][0] = s_w[ra * 32 + g0];
            qf[c][1] = s_w[(ra + 8) * 32 + g0];
            qf[c][2] = s_w[ra * 32 + g1];
            qf[c][3] = s_w[(ra + 8) * 32 + g1];
        }
        __syncthreads();
    }

    float m0s = -1e30f, m1s = -1e30f;
    float l0 = 0.f, l1 = 0.f;
    float acc_o[8][4];
#pragma unroll
    for (int nt = 0; nt < 8; nt++)
#pragma unroll
        for (int j = 0; j < 4; j++) acc_o[nt][j] = 0.f;

    const int nkb = blockIdx.x * 2 + 2;
    const __half* Kg = qkv + bbase + 1024 + hcol;
    const __half* Vg = vt + (long long)z * HDn * Tn;
    const int rga = m0 + w * 16 + q;
    const int rgb = rga + 8;

    const unsigned kBase = smem_u32(s_w) + 16384;
    const unsigned vBase = smem_u32(s_w) + 24576;

    for (int it = 0; it < nkb; it++) {
        {
#pragma unroll
            for (int i = 0; i < 2; i++) {
                int idx = tid + 256 * i;
                int r = idx >> 3, ch = idx & 7;
                unsigned sw = r * 32 + (((unsigned)(ch * 4)) ^ ((unsigned)((r & 7) * 4)));
                cp16(smem_u32(s_w + 4096 + sw),
                     Kg + (long long)(it * 64 + r) * NQKV + ch * 8);
                cp16(smem_u32(s_w + 6144 + sw),
                     Vg + (long long)r * Tn + it * 64 + ch * 8);
            }
            CP_COMMIT();
            CP_WAIT(0);
        }
        __syncthreads();

        float s[8][4];
#pragma unroll
        for (int nt = 0; nt < 8; nt++)
#pragma unroll
            for (int j = 0; j < 4; j++) s[nt][j] = 0.f;

#pragma unroll
        for (int c = 0; c < 4; c++) {
            unsigned bbf[8][2];
            const unsigned swzB = (unsigned)(((2 * c + caB) ^ ri) << 4);
#pragma unroll
            for (int p = 0; p < 4; p++) {
                unsigned addr = kBase + (bRow + p * 16) * 128 + swzB;
                LDSM_X4(bbf[2 * p][0], bbf[2 * p][1],
                        bbf[2 * p + 1][0], bbf[2 * p + 1][1], addr);
            }
#pragma unroll
            for (int nt = 0; nt < 8; nt++)
                MMA_FP16(s[nt], qf[c], bbf[nt]);
        }

        const int cb = kb * 2;
        if (it * 64 + 63 > rga) {
#pragma unroll
            for (int nt = 0; nt < 8; nt++) {
                int cg = it * 64 + nt * 8 + cb;
                if (cg > rga)     s[nt][0] = -1e30f;
                if (cg + 1 > rga) s[nt][1] = -1e30f;
                if (cg > rgb)     s[nt][2] = -1e30f;
                if (cg + 1 > rgb) s[nt][3] = -1e30f;
            }
        }

        float ml0 = -1e30f, ml1 = -1e30f;
#pragma unroll
        for (int nt = 0; nt < 8; nt++) {
            ml0 = fmaxf(ml0, fmaxf(s[nt][0], s[nt][1]));
            ml1 = fmaxf(ml1, fmaxf(s[nt][2], s[nt][3]));
        }
        ml0 = fmaxf(ml0, __shfl_xor_sync(0xffffffffu, ml0, 1));
        ml0 = fmaxf(ml0, __shfl_xor_sync(0xffffffffu, ml0, 2));
        ml1 = fmaxf(ml1, __shfl_xor_sync(0xffffffffu, ml1, 1));
        ml1 = fmaxf(ml1, __shfl_xor_sync(0xffffffffu, ml1, 2));
        float mn0 = fmaxf(m0s, ml0), mn1 = fmaxf(m1s, ml1);
        float al0 = __expf(m0s - mn0), al1 = __expf(m1s - mn1);
        m0s = mn0; m1s = mn1;

        float rs0 = 0.f, rs1 = 0.f;
#pragma unroll
        for (int nt = 0; nt < 8; nt++) {
            s[nt][0] = __expf(s[nt][0] - mn0);
            s[nt][1] = __expf(s[nt][1] - mn0);
            s[nt][2] = __expf(s[nt][2] - mn1);
            s[nt][3] = __expf(s[nt][3] - mn1);
            rs0 += s[nt][0] + s[nt][1];
            rs1 += s[nt][2] + s[nt][3];
        }
        rs0 += __shfl_xor_sync(0xffffffffu, rs0, 1);
        rs0 += __shfl_xor_sync(0xffffffffu, rs0, 2);
        rs1 += __shfl_xor_sync(0xffffffffu, rs1, 1);
        rs1 += __shfl_xor_sync(0xffffffffu, rs1, 2);
        l0 = l0 * al0 + rs0;
        l1 = l1 * al1 + rs1;
#pragma unroll
        for (int nt = 0; nt < 8; nt++) {
            acc_o[nt][0] *= al0; acc_o[nt][1] *= al0;
            acc_o[nt][2] *= al1; acc_o[nt][3] *= al1;
        }

#pragma unroll
        for (int c = 0; c < 4; c++) {
            unsigned pa[4];
            pa[0] = pack_h2(s[2 * c][0],     s[2 * c][1]);
            pa[1] = pack_h2(s[2 * c][2],     s[2 * c][3]);
            pa[2] = pack_h2(s[2 * c + 1][0], s[2 * c + 1][1]);
            pa[3] = pack_h2(s[2 * c + 1][2], s[2 * c + 1][3]);
            unsigned bbf[8][2];
            const unsigned swzB = (unsigned)(((2 * c + caB) ^ ri) << 4);
#pragma unroll
            for (int p = 0; p < 4; p++) {
                unsigned addr = vBase + (bRow + p * 16) * 128 + swzB;
                LDSM_X4(bbf[2 * p][0], bbf[2 * p][1],
                        bbf[2 * p + 1][0], bbf[2 * p + 1][1], addr);
            }
#pragma unroll
            for (int nt = 0; nt < 8; nt++)
                MMA_FP16(acc_o[nt], pa, bbf[nt]);
        }
        __syncthreads();
    }

    const float i0 = 1.f / l0, i1 = 1.f / l1;
    __half* op = att + (long long)(z >> 4) * Tn * Dn + (z & 15) * HDn;
    const int cb = kb * 2;
#pragma unroll
    for (int nt = 0; nt < 8; nt++) {
        *reinterpret_cast<unsigned*>(op + (long long)rga * Dn + nt * 8 + cb) =
            pack_h2(acc_o[nt][0] * i0, acc_o[nt][1] * i0);
        *reinterpret_cast<unsigned*>(op + (long long)rgb * Dn + nt * 8 + cb) =
            pack_h2(acc_o[nt][2] * i1, acc_o[nt][3] * i1);
    }
}

// ---------------------------------------------------------------------------
// LayerNorm over last dim (1024), output fp16.
// ---------------------------------------------------------------------------
__launch_bounds__(256)
__global__ void ln_kernel(const float* __restrict__ x,
                          const float* __restrict__ g,
                          const float* __restrict__ be,
                          __half* __restrict__ outp)
{
    long long row = blockIdx.x;
    const float* xr = x + row * Dn;
    int tid = threadIdx.x;

    float v[4];
    float s = 0.f;
#pragma unroll
    for (int i = 0; i < 4; i++) { v[i] = xr[tid + 256 * i]; s += v[i]; }

    __shared__ float red[8];
    __shared__ float sh_mu, sh_rstd;

#pragma unroll
    for (int o = 16; o > 0; o >>= 1) s += __shfl_xor_sync(0xffffffffu, s, o);
    if ((tid & 31) == 0) red[tid >> 5] = s;
    __syncthreads();
    if (tid == 0) {
        float t = 0.f;
        for (int i = 0; i < 8; i++) t += red[i];
        sh_mu = t * (1.0f / Dn);
    }
    __syncthreads();
    float mu = sh_mu;

    float ss = 0.f;
#pragma unroll
    for (int i = 0; i < 4; i++) { float d = v[i] - mu; ss += d * d; }
#pragma unroll
    for (int o = 16; o > 0; o >>= 1) ss += __shfl_xor_sync(0xffffffffu, ss, o);
    if ((tid & 31) == 0) red[tid >> 5] = ss;
    __syncthreads();
    if (tid == 0) {
        float t = 0.f;
        for (int i = 0; i < 8; i++) t += red[i];
        sh_rstd = rsqrtf(t * (1.0f / Dn) + 1e-5f);
    }
    __syncthreads();
    float rstd = sh_rstd;

#pragma unroll
    for (int i = 0; i < 4; i++) {
        int c = tid + 256 * i;
        outp[row * Dn + c] = __float2half_rn((v[i] - mu) * rstd * g[c] + be[c]);
    }
}

// ---------------------------------------------------------------------------
extern "C" void kernel_launch(void* const* d_in, const int* in_sizes, int n_in,
                              void* d_out, int out_size)
{
    const float* x   = (const float*)d_in[0];
    const float* Wq  = (const float*)d_in[1];
    const float* Wk  = (const float*)d_in[2];
    const float* Wv  = (const float*)d_in[3];
    const float* Wo  = (const float*)d_in[4];
    const float* bo  = (const float*)d_in[5];
    const float* W1  = (const float*)d_in[6];
    const float* b1  = (const float*)d_in[7];
    const float* W2  = (const float*)d_in[8];
    const float* b2  = (const float*)d_in[9];
    const float* g1  = (const float*)d_in[10];
    const float* be1 = (const float*)d_in[11];
    const float* g2  = (const float*)d_in[12];
    const float* be2 = (const float*)d_in[13];
    float* out = (float*)d_out;

    float *x2;
    __half *h1, *qkv, *vt, *att, *h2, *mid;
    __half *wqkvT, *woT, *w1T, *w2T;
    cudaGetSymbolAddress((void**)&h1,   g_h1);
    cudaGetSymbolAddress((void**)&qkv,  g_qkv);
    cudaGetSymbolAddress((void**)&vt,   g_vt);
    cudaGetSymbolAddress((void**)&att,  g_att);
    cudaGetSymbolAddress((void**)&x2,   g_x2);
    cudaGetSymbolAddress((void**)&h2,   g_h2);
    cudaGetSymbolAddress((void**)&mid,  g_mid);
    cudaGetSymbolAddress((void**)&wqkvT, g_wqkvT);
    cudaGetSymbolAddress((void**)&woT,  g_woT);
    cudaGetSymbolAddress((void**)&w1T,  g_w1T);
    cudaGetSymbolAddress((void**)&w2T,  g_w2T);

    const int GSMEM = 2 * 12288 * 4;   // 96 KB (2 stages x 48 KB)
    cudaFuncSetAttribute(gemm_fp16<0>, cudaFuncAttributeMaxDynamicSharedMemorySize, GSMEM);
    cudaFuncSetAttribute(gemm_fp16<1>, cudaFuncAttributeMaxDynamicSharedMemorySize, GSMEM);
    cudaFuncSetAttribute(gemm_fp16<2>, cudaFuncAttributeMaxDynamicSharedMemorySize, GSMEM);

    dim3 blk(256);
    dim3 tblk(32, 8);

    // ---- weight transposes (fp32 -> fp16) into fused [3072][1024] B operand.
    // Wq scaled by 2^-5 (exact exponent shift) = folds the attention scale into q.
    transpose_f2h<<<dim3(HDn / 32, Dn / 32, Hn), tblk>>>(
        Wq, wqkvT + 0 * Dn * Dn, HDn, (long long)Dn * HDn, Dn, (long long)HDn * Dn,
        0.03125f);
    transpose_f2h<<<dim3(HDn / 32, Dn / 32, Hn), tblk>>>(
        Wk, wqkvT + 1 * Dn * Dn, HDn, (long long)Dn * HDn, Dn, (long long)HDn * Dn,
        1.0f);
    transpose_f2h<<<dim3(HDn / 32, Dn / 32, Hn), tblk>>>(
        Wv, wqkvT + 2 * Dn * Dn, HDn, (long long)Dn * HDn, Dn, (long long)HDn * Dn,
        1.0f);
    transpose_f2h<<<dim3(Dn / 32, Dn / 32, 1), tblk>>>(
        Wo, woT, Dn, 0LL, Dn, 0LL, 1.0f);
    transpose_f2h<<<dim3(4 * Dn / 32, Dn / 32, 1), tblk>>>(
        W1, w1T, 4 * Dn, 0LL, Dn, 0LL, 1.0f);
    transpose_f2h<<<dim3(Dn / 32, 4 * Dn / 32, 1), tblk>>>(
        W2, w2T, Dn, 0LL, 4 * Dn, 0LL, 1.0f);

    // ---- LN1: x -> h1 (fp16)
    ln_kernel<<<ROWS, blk>>>(x, g1, be1, h1);

    // ---- fused QKV as ONE exact-size GEMM: qkv[4096][3072] = h1 @ wqkvT^T (fp16 out)
    gemm_fp16<0><<<dim3(NQKV / 256, ROWS / 128, 1), blk, GSMEM>>>(
        h1, wqkvT, nullptr, qkv, nullptr, nullptr,
        NQKV, Dn, Dn, Dn, NQKV);

    // ---- V transpose (fp16): qkv cols [2048 + h*64 ..] -> vt [z][HD][T]
    transpose_h<<<dim3(HDn / 32, Tn / 32, ZHD), tblk>>>(
        qkv + 2048, vt, NQKV,
        (long long)Tn * NQKV, Hn, (long long)HDn, Hn,
        Tn, (long long)HDn * Tn);

    // ---- flash attention (fp16) -> att (fp16, concat layout)
    flash_fp16<<<dim3(Tn / 128, ZHD), blk>>>(qkv, vt, att);

    // ---- O projection + bias + residual: x2 = x + att @ Wo + bo (fp32 out)
    gemm_fp16<2><<<dim3(Dn / 256, ROWS / 128, 1), blk, GSMEM>>>(
        att, woT, x2, nullptr, bo, x,
        Dn, Dn, Dn, Dn, Dn);

    // ---- LN2: x2 -> h2 (fp16)
    ln_kernel<<<ROWS, blk>>>(x2, g2, be2, h2);

    // ---- FFN1: mid = relu(h2 @ W1 + b1) (fp16 out)
    gemm_fp16<1><<<dim3(4 * Dn / 256, ROWS / 128, 1), blk, GSMEM>>>(
        h2, w1T, nullptr, mid, b1, nullptr,
        4 * Dn, Dn, Dn, Dn, 4 * Dn);

    // ---- FFN2: out = x2 + mid @ W2 + b2 (fp32 out)
    gemm_fp16<2><<<dim3(Dn / 256, ROWS / 128, 1), blk, GSMEM>>>(
        mid, w2T, out, nullptr, b2, x2,
        Dn, 4 * Dn, 4 * Dn, 4 * Dn, Dn);
}

// round 15
// speedup vs baseline: 1.0648x; 1.0648x over previous
#include <cuda_runtime.h>
#include <cuda_fp16.h>

// Problem constants
#define Tn   2048
#define Dn   1024
#define Hn   16
#define HDn  64
#define Bn   2
#define ROWS (Bn * Tn)   // 4096
#define ZHD  (Bn * Hn)   // 32
#define NQKV 3072        // q|k|v fused output width

// ---------------- scratch (static device globals; no allocations) ----------
__device__ __half g_h1 [ROWS * Dn];
__device__ __half g_qkv[ROWS * NQKV];            // [b*T][3072]: q|k|v (q pre-scaled via Wq)
__device__ __half g_vt [ZHD * HDn * Tn];         // V^T per (b,h)
__device__ __half g_att[ROWS * Dn];
__device__ float  g_x2 [ROWS * Dn];
__device__ __half g_h2 [ROWS * Dn];
__device__ __half g_mid[ROWS * 4 * Dn];
__device__ __half g_wqkvT[NQKV * Dn];            // [3072][1024] fused B operand
__device__ __half g_woT [Dn * Dn];
__device__ __half g_w1T [4 * Dn * Dn];           // [4D][D]
__device__ __half g_w2T [4 * Dn * Dn];           // [D][4D]

// ---------------------------------------------------------------------------
__device__ __forceinline__ unsigned smem_u32(const void* p) {
    return (unsigned)__cvta_generic_to_shared(p);
}
__device__ __forceinline__ void cp16(unsigned dst, const void* src) {
    asm volatile("cp.async.cg.shared.global [%0],[%1],16;\n" :: "r"(dst), "l"(src));
}
#define CP_COMMIT()  asm volatile("cp.async.commit_group;" ::: "memory")
#define CP_WAIT(n)   asm volatile("cp.async.wait_group %0;" :: "n"(n) : "memory")

#define MMA_FP16(d, a, b) \
    asm volatile("mma.sync.aligned.m16n8k16.row.col.f32.f16.f16.f32 " \
                 "{%0,%1,%2,%3},{%4,%5,%6,%7},{%8,%9},{%0,%1,%2,%3};\n" \
                 : "+f"((d)[0]), "+f"((d)[1]), "+f"((d)[2]), "+f"((d)[3]) \
                 : "r"((a)[0]), "r"((a)[1]), "r"((a)[2]), "r"((a)[3]), \
                   "r"((b)[0]), "r"((b)[1]))

// Warp-collective fragment load: 4 x m8n8 b16 matrices.
#define LDSM_X4(r0, r1, r2, r3, addr) \
    asm volatile("ldmatrix.sync.aligned.m8n8.x4.shared.b16 {%0,%1,%2,%3},[%4];\n" \
                 : "=r"(r0), "=r"(r1), "=r"(r2), "=r"(r3) : "r"(addr))

__device__ __forceinline__ unsigned pack_h2(float a, float b) {
    __half2 h = __floats2half2_rn(a, b);
    return *reinterpret_cast<unsigned*>(&h);
}

// ---------------------------------------------------------------------------
// Fused weight transposes (ONE launch): fp32 [R][C] -> fp16 [C][R] for
// Wq/Wk/Wv (-> fused wqkvT, Wq scaled 2^-5), Wo, W1, W2. 12288 tile-blocks.
// ---------------------------------------------------------------------------
__global__ void transpose_weights(const float* __restrict__ Wq,
                                  const float* __restrict__ Wk,
                                  const float* __restrict__ Wv,
                                  const float* __restrict__ Wo,
                                  const float* __restrict__ W1,
                                  const float* __restrict__ W2,
                                  __half* __restrict__ wqkvT,
                                  __half* __restrict__ woT,
                                  __half* __restrict__ w1T,
                                  __half* __restrict__ w2T)
{
    __shared__ float t[32][33];
    const int tb = blockIdx.x;
    const float* in;
    __half* outp;
    int ldin, ldout, cx, cy;
    float scale = 1.0f;

    if (tb < 3072) {
        // Wq/Wk/Wv: per head [D][HD] -> wqkvT rows seg*1024 + h*64
        const int seg = tb / 1024;
        const int r   = tb % 1024;
        const int z   = r / 64;            // head
        const int rr  = r % 64;
        cx = rr & 1;                       // HD tiles: 2
        cy = rr >> 1;                      // D tiles: 32
        const float* W = (seg == 0) ? Wq : (seg == 1) ? Wk : Wv;
        in   = W + (long long)z * Dn * HDn;
        ldin = HDn;
        outp  = wqkvT + (long long)seg * Dn * Dn + (long long)z * HDn * Dn;
        ldout = Dn;
        if (seg == 0) scale = 0.03125f;    // fold attention scale into Wq
    } else if (tb < 4096) {
        const int r = tb - 3072;
        cx = r & 31; cy = r >> 5;          // [D][D]
        in = Wo; ldin = Dn; outp = woT; ldout = Dn;
    } else if (tb < 8192) {
        const int r = tb - 4096;
        cx = r & 127; cy = r >> 7;         // [D][4D]: C tiles 128, R tiles 32
        in = W1; ldin = 4 * Dn; outp = w1T; ldout = Dn;
    } else {
        const int r = tb - 8192;
        cx = r & 31; cy = r >> 5;          // [4D][D]: C tiles 32, R tiles 128
        in = W2; ldin = Dn; outp = w2T; ldout = 4 * Dn;
    }

    const int c0 = cx * 32, r0 = cy * 32;
    const int tx = threadIdx.x, ty = threadIdx.y;
#pragma unroll
    for (int i = 0; i < 32; i += 8)
        t[ty + i][tx] = in[(long long)(r0 + ty + i) * ldin + c0 + tx];
    __syncthreads();
#pragma unroll
    for (int i = 0; i < 32; i += 8)
        outp[(long long)(c0 + ty + i) * ldout + r0 + tx] =
            __float2half_rn(t[tx][ty + i] * scale);
}

// transpose fp16 -> fp16: in tile [R][C] -> out [C][R]; z offsets (z/dz)*sIn1+(z%mz)*sIn2.
__global__ void transpose_h(const __half* __restrict__ in,
                            __half* __restrict__ outp,
                            int ldin, long long sIn1, int dz, long long sIn2, int mz,
                            int ldout, long long sOut)
{
    __shared__ __half t[32][34];
    int z = blockIdx.z;
    in   += (long long)(z / dz) * sIn1 + (long long)(z % mz) * sIn2;
    outp += (long long)z * sOut;
    int c0 = blockIdx.x * 32, r0 = blockIdx.y * 32;
    int tx = threadIdx.x, ty = threadIdx.y;
#pragma unroll
    for (int i = 0; i < 32; i += 8)
        t[ty + i][tx] = in[(long long)(r0 + ty + i) * ldin + c0 + tx];
    __syncthreads();
#pragma unroll
    for (int i = 0; i < 32; i += 8)
        outp[(long long)(c0 + ty + i) * ldout + r0 + tx] = t[tx][ty + i];
}

// ---------------------------------------------------------------------------
// gemm_fp16: single-pass FP16 GEMM (fp32 accum), ldmatrix fragment loads.
//   C = A @ B^T (+epi). A fp16 [M,K]; B fp16 [N,K].
//   EPI: 0 -> fp16 C; 1 -> bias+relu -> fp16 C; 2 -> bias+residual -> fp32 C.
// BM=128, BN=128, BK=64, 256 thr (warps 2m x 4n, warp tile 64x32),
// 2-stage cp.async double buffer, XOR-swizzled smem (LDSM-compatible).
// ---------------------------------------------------------------------------
template <int EPI>
__launch_bounds__(256, 2)
__global__ void gemm_fp16(const __half* __restrict__ A,
                          const __half* __restrict__ B,
                          float* __restrict__ C,
                          __half* __restrict__ Ch,
                          const float* __restrict__ bias,
                          const float* __restrict__ res,
                          int N, int K, int lda, int ldb, int ldc)
{
    extern __shared__ unsigned sm[];   // stage s: A at s*8192 words, B at +4096 words

    const int m0 = blockIdx.y * 128;
    const int n0 = blockIdx.x * 128;

    const int tid  = threadIdx.x;
    const int lane = tid & 31;
    const int w    = tid >> 5;
    const int wm   = (w & 1) * 64;
    const int wn   = (w >> 1) * 32;
    const int q    = lane >> 2;
    const int kb   = lane & 3;
    const int nk   = K / 64;

    // ldmatrix lane mapping
    const int mi = lane >> 3;          // matrix index group 0..3
    const int ri = lane & 7;           // row within matrix
    const unsigned aRow = wm + (mi & 1) * 8 + ri;   // + mt*16
    const unsigned bRow = wn + (mi >> 1) * 8 + ri;  // + p*16
    const int caA = mi >> 1;           // chunk half for A (k lo/hi)
    const int caB = mi & 1;            // chunk half for B

    // loader: thread handles rows (tid>>3)+32i, 16B chunk tid&7
    const int lrow = tid >> 3;
    const int lg   = tid & 7;
    const unsigned lsw = ((unsigned)(lg * 4)) ^ ((unsigned)((lrow & 7) * 4));

    float acc[4][4][4];
#pragma unroll
    for (int mt = 0; mt < 4; mt++)
#pragma unroll
        for (int nt = 0; nt < 4; nt++)
#pragma unroll
            for (int j = 0; j < 4; j++) acc[mt][nt][j] = 0.f;

    auto load_stage = [&](int st, int kt) {
        unsigned* sb = sm + st * 8192;
        const int k0 = kt * 64;
#pragma unroll
        for (int i = 0; i < 4; i++) {
            int row = lrow + 32 * i;
            unsigned off = row * 32 + lsw;
            cp16(smem_u32(sb + off),        A + (long long)(m0 + row) * lda + k0 + lg * 8);
            cp16(smem_u32(sb + 4096 + off), B + (long long)(n0 + row) * ldb + k0 + lg * 8);
        }
        CP_COMMIT();
    };

    load_stage(0, 0);

    const unsigned sbase0 = smem_u32(sm);

    for (int kt = 0; kt < nk; kt++) {
        if (kt + 1 < nk) {
            load_stage((kt + 1) & 1, kt + 1);
            CP_WAIT(1);
        } else {
            CP_WAIT(0);
        }
        __syncthreads();

        const unsigned sA = sbase0 + (kt & 1) * 32768;         // stage A byte base
        const unsigned sB = sA + 16384;                        // stage B byte base
#pragma unroll
        for (int c = 0; c < 4; c++) {              // 4 x k16 chunks
            unsigned a[4][4], b[4][2];
            const unsigned swzA = (unsigned)(((2 * c + caA) ^ ri) << 4);
            const unsigned swzB = (unsigned)(((2 * c + caB) ^ ri) << 4);
#pragma unroll
            for (int mt = 0; mt < 4; mt++) {
                unsigned addr = sA + (aRow + mt * 16) * 128 + swzA;
                LDSM_X4(a[mt][0], a[mt][1], a[mt][2], a[mt][3], addr);
            }
#pragma unroll
            for (int p = 0; p < 2; p++) {
                unsigned addr = sB + (bRow + p * 16) * 128 + swzB;
                LDSM_X4(b[2 * p][0], b[2 * p][1], b[2 * p + 1][0], b[2 * p + 1][1], addr);
            }
#pragma unroll
            for (int mt = 0; mt < 4; mt++)
#pragma unroll
                for (int nt = 0; nt < 4; nt++)
                    MMA_FP16(acc[mt][nt], a[mt], b[nt]);
        }
        __syncthreads();
    }

    // ---- epilogue
#pragma unroll
    for (int mt = 0; mt < 4; mt++)
#pragma unroll
        for (int nt = 0; nt < 4; nt++) {
            const float* a4 = acc[mt][nt];
            const long long r0 = m0 + wm + mt * 16 + q;
            const long long r1 = r0 + 8;
            const int cc = n0 + wn + nt * 8 + kb * 2;
            if (EPI == 0) {
                *reinterpret_cast<unsigned*>(&Ch[r0 * ldc + cc]) = pack_h2(a4[0], a4[1]);
                *reinterpret_cast<unsigned*>(&Ch[r1 * ldc + cc]) = pack_h2(a4[2], a4[3]);
            } else if (EPI == 1) {
                float2 bv = *reinterpret_cast<const float2*>(&bias[cc]);
                *reinterpret_cast<unsigned*>(&Ch[r0 * ldc + cc]) =
                    pack_h2(fmaxf(a4[0] + bv.x, 0.f), fmaxf(a4[1] + bv.y, 0.f));
                *reinterpret_cast<unsigned*>(&Ch[r1 * ldc + cc]) =
                    pack_h2(fmaxf(a4[2] + bv.x, 0.f), fmaxf(a4[3] + bv.y, 0.f));
            } else {
                float2 bv = *reinterpret_cast<const float2*>(&bias[cc]);
                float2 q0 = *reinterpret_cast<const float2*>(&res[r0 * ldc + cc]);
                float2 q1 = *reinterpret_cast<const float2*>(&res[r1 * ldc + cc]);
                *reinterpret_cast<float2*>(&C[r0 * ldc + cc]) =
                    make_float2(a4[0] + bv.x + q0.x, a4[1] + bv.y + q0.y);
                *reinterpret_cast<float2*>(&C[r1 * ldc + cc]) =
                    make_float2(a4[2] + bv.x + q1.x, a4[3] + bv.y + q1.y);
            }
        }
}

// ---------------------------------------------------------------------------
// Flash attention, FP16 operands / fp32 softmax+accum; ldmatrix K/V loads.
// Q pre-scaled by 2^-5 (folded into Wq). grid = (Tn/128, ZHD), block = 256.
// Static smem: 8192 words = 32 KB (Q 0..4095, K 4096..6143, V 6144..8191).
// ---------------------------------------------------------------------------
__launch_bounds__(256)
__global__ void flash_fp16(const __half* __restrict__ qkv,
                           const __half* __restrict__ vt,
                           __half* __restrict__ att)
{
    __shared__ __align__(16) unsigned s_w[8192];

    const int z  = blockIdx.y;
    const int m0 = blockIdx.x * 128;
    const int tid = threadIdx.x, lane = tid & 31, w = tid >> 5;
    const int q  = lane >> 2;
    const int kb = lane & 3;
    const unsigned qx = (unsigned)(q << 2);

    // ldmatrix lane mapping (B-style: tile pair p, chunk half caB)
    const int mi = lane >> 3;
    const int ri = lane & 7;
    const unsigned bRow = (unsigned)((mi >> 1) * 8 + ri);   // + p*16
    const int caB = mi & 1;

    const long long bbase = (long long)(z >> 4) * Tn * NQKV;   // batch row base
    const int hcol = (z & 15) * HDn;                           // head column

    // ---- stage Q (128x64 halfs, swizzled), extract fp16 A-fragments (scalar, once)
    unsigned qf[4][4];
    {
        const __half* Qg = qkv + bbase + (long long)m0 * NQKV + hcol;
#pragma unroll
        for (int i = 0; i < 4; i++) {
            int idx = tid + 256 * i;           // 0..1023 chunks
            int r = idx >> 3, ch = idx & 7;
            unsigned sw = r * 32 + (((unsigned)(ch * 4)) ^ ((unsigned)((r & 7) * 4)));
            cp16(smem_u32(s_w + sw), Qg + (long long)r * NQKV + ch * 8);
        }
        CP_COMMIT();
        CP_WAIT(0);
        __syncthreads();
        const int ra = w * 16 + q;
#pragma unroll
        for (int c = 0; c < 4; c++) {
            const unsigned g0 = ((unsigned)(c * 8) ^ qx) + kb;
            const unsigned g1 = ((unsigned)(c * 8 + 4) ^ qx) + kb;
            qf[c][0] = s_w[ra * 32 + g0];
            qf[c][1] = s_w[(ra + 8) * 32 + g0];
            qf[c][2] = s_w[ra * 32 + g1];
            qf[c][3] = s_w[(ra + 8) * 32 + g1];
        }
        __syncthreads();
    }

    float m0s = -1e30f, m1s = -1e30f;
    float l0 = 0.f, l1 = 0.f;
    float acc_o[8][4];
#pragma unroll
    for (int nt = 0; nt < 8; nt++)
#pragma unroll
        for (int j = 0; j < 4; j++) acc_o[nt][j] = 0.f;

    const int nkb = blockIdx.x * 2 + 2;
    const __half* Kg = qkv + bbase + 1024 + hcol;
    const __half* Vg = vt + (long long)z * HDn * Tn;
    const int rga = m0 + w * 16 + q;
    const int rgb = rga + 8;

    const unsigned kBase = smem_u32(s_w) + 16384;   // K tile byte base (word 4096)
    const unsigned vBase = smem_u32(s_w) + 24576;   // V tile byte base (word 6144)

    for (int it = 0; it < nkb; it++) {
        // ---- load K (64x64) and V^T (64x64) fp16 tiles, swizzled
        {
#pragma unroll
            for (int i = 0; i < 2; i++) {
                int idx = tid + 256 * i;       // 0..511 chunks
                int r = idx >> 3, ch = idx & 7;
                unsigned sw = r * 32 + (((unsigned)(ch * 4)) ^ ((unsigned)((r & 7) * 4)));
                cp16(smem_u32(s_w + 4096 + sw),
                     Kg + (long long)(it * 64 + r) * NQKV + ch * 8);
                cp16(smem_u32(s_w + 6144 + sw),
                     Vg + (long long)r * Tn + it * 64 + ch * 8);
            }
            CP_COMMIT();
            CP_WAIT(0);
        }
        __syncthreads();

        // ---- S = Q K^T (fp16, fp32 accum); K frags via ldmatrix
        float s[8][4];
#pragma unroll
        for (int nt = 0; nt < 8; nt++)
#pragma unroll
            for (int j = 0; j < 4; j++) s[nt][j] = 0.f;

#pragma unroll
        for (int c = 0; c < 4; c++) {
            unsigned bbf[8][2];
            const unsigned swzB = (unsigned)(((2 * c + caB) ^ ri) << 4);
#pragma unroll
            for (int p = 0; p < 4; p++) {
                unsigned addr = kBase + (bRow + p * 16) * 128 + swzB;
                LDSM_X4(bbf[2 * p][0], bbf[2 * p][1],
                        bbf[2 * p + 1][0], bbf[2 * p + 1][1], addr);
            }
#pragma unroll
            for (int nt = 0; nt < 8; nt++)
                MMA_FP16(s[nt], qf[c], bbf[nt]);
        }

        // ---- causal mask
        const int cb = kb * 2;
        if (it * 64 + 63 > rga) {
#pragma unroll
            for (int nt = 0; nt < 8; nt++) {
                int cg = it * 64 + nt * 8 + cb;
                if (cg > rga)     s[nt][0] = -1e30f;
                if (cg + 1 > rga) s[nt][1] = -1e30f;
                if (cg > rgb)     s[nt][2] = -1e30f;
                if (cg + 1 > rgb) s[nt][3] = -1e30f;
            }
        }

        // ---- online softmax (fp32)
        float ml0 = -1e30f, ml1 = -1e30f;
#pragma unroll
        for (int nt = 0; nt < 8; nt++) {
            ml0 = fmaxf(ml0, fmaxf(s[nt][0], s[nt][1]));
            ml1 = fmaxf(ml1, fmaxf(s[nt][2], s[nt][3]));
        }
        ml0 = fmaxf(ml0, __shfl_xor_sync(0xffffffffu, ml0, 1));
        ml0 = fmaxf(ml0, __shfl_xor_sync(0xffffffffu, ml0, 2));
        ml1 = fmaxf(ml1, __shfl_xor_sync(0xffffffffu, ml1, 1));
        ml1 = fmaxf(ml1, __shfl_xor_sync(0xffffffffu, ml1, 2));
        float mn0 = fmaxf(m0s, ml0), mn1 = fmaxf(m1s, ml1);
        float al0 = __expf(m0s - mn0), al1 = __expf(m1s - mn1);
        m0s = mn0; m1s = mn1;

        float rs0 = 0.f, rs1 = 0.f;
#pragma unroll
        for (int nt = 0; nt < 8; nt++) {
            s[nt][0] = __expf(s[nt][0] - mn0);
            s[nt][1] = __expf(s[nt][1] - mn0);
            s[nt][2] = __expf(s[nt][2] - mn1);
            s[nt][3] = __expf(s[nt][3] - mn1);
            rs0 += s[nt][0] + s[nt][1];
            rs1 += s[nt][2] + s[nt][3];
        }
        rs0 += __shfl_xor_sync(0xffffffffu, rs0, 1);
        rs0 += __shfl_xor_sync(0xffffffffu, rs0, 2);
        rs1 += __shfl_xor_sync(0xffffffffu, rs1, 1);
        rs1 += __shfl_xor_sync(0xffffffffu, rs1, 2);
        l0 = l0 * al0 + rs0;
        l1 = l1 * al1 + rs1;
#pragma unroll
        for (int nt = 0; nt < 8; nt++) {
            acc_o[nt][0] *= al0; acc_o[nt][1] *= al0;
            acc_o[nt][2] *= al1; acc_o[nt][3] *= al1;
        }

        // ---- P C-frag -> fp16 A-frags (k16 identity) and PV; V frags via ldmatrix
#pragma unroll
        for (int c = 0; c < 4; c++) {
            unsigned pa[4];
            pa[0] = pack_h2(s[2 * c][0],     s[2 * c][1]);
            pa[1] = pack_h2(s[2 * c][2],     s[2 * c][3]);
            pa[2] = pack_h2(s[2 * c + 1][0], s[2 * c + 1][1]);
            pa[3] = pack_h2(s[2 * c + 1][2], s[2 * c + 1][3]);
            unsigned bbf[8][2];
            const unsigned swzB = (unsigned)(((2 * c + caB) ^ ri) << 4);
#pragma unroll
            for (int p = 0; p < 4; p++) {
                unsigned addr = vBase + (bRow + p * 16) * 128 + swzB;
                LDSM_X4(bbf[2 * p][0], bbf[2 * p][1],
                        bbf[2 * p + 1][0], bbf[2 * p + 1][1], addr);
            }
#pragma unroll
            for (int nt = 0; nt < 8; nt++)
                MMA_FP16(acc_o[nt], pa, bbf[nt]);
        }
        __syncthreads();     // protect smem before next tile's cp.async
    }

    // ---- epilogue: normalize, write fp16 concat layout [b][t][h*64+e]
    const float i0 = 1.f / l0, i1 = 1.f / l1;
    __half* op = att + (long long)(z >> 4) * Tn * Dn + (z & 15) * HDn;
    const int cb = kb * 2;
#pragma unroll
    for (int nt = 0; nt < 8; nt++) {
        *reinterpret_cast<unsigned*>(op + (long long)rga * Dn + nt * 8 + cb) =
            pack_h2(acc_o[nt][0] * i0, acc_o[nt][1] * i0);
        *reinterpret_cast<unsigned*>(op + (long long)rgb * Dn + nt * 8 + cb) =
            pack_h2(acc_o[nt][2] * i1, acc_o[nt][3] * i1);
    }
}

// ---------------------------------------------------------------------------
// LayerNorm over last dim (1024), output fp16.
// ---------------------------------------------------------------------------
__launch_bounds__(256)
__global__ void ln_kernel(const float* __restrict__ x,
                          const float* __restrict__ g,
                          const float* __restrict__ be,
                          __half* __restrict__ outp)
{
    long long row = blockIdx.x;
    const float* xr = x + row * Dn;
    int tid = threadIdx.x;

    float v[4];
    float s = 0.f;
#pragma unroll
    for (int i = 0; i < 4; i++) { v[i] = xr[tid + 256 * i]; s += v[i]; }

    __shared__ float red[8];
    __shared__ float sh_mu, sh_rstd;

#pragma unroll
    for (int o = 16; o > 0; o >>= 1) s += __shfl_xor_sync(0xffffffffu, s, o);
    if ((tid & 31) == 0) red[tid >> 5] = s;
    __syncthreads();
    if (tid == 0) {
        float t = 0.f;
        for (int i = 0; i < 8; i++) t += red[i];
        sh_mu = t * (1.0f / Dn);
    }
    __syncthreads();
    float mu = sh_mu;

    float ss = 0.f;
#pragma unroll
    for (int i = 0; i < 4; i++) { float d = v[i] - mu; ss += d * d; }
#pragma unroll
    for (int o = 16; o > 0; o >>= 1) ss += __shfl_xor_sync(0xffffffffu, ss, o);
    if ((tid & 31) == 0) red[tid >> 5] = ss;
    __syncthreads();
    if (tid == 0) {
        float t = 0.f;
        for (int i = 0; i < 8; i++) t += red[i];
        sh_rstd = rsqrtf(t * (1.0f / Dn) + 1e-5f);
    }
    __syncthreads();
    float rstd = sh_rstd;

#pragma unroll
    for (int i = 0; i < 4; i++) {
        int c = tid + 256 * i;
        outp[row * Dn + c] = __float2half_rn((v[i] - mu) * rstd * g[c] + be[c]);
    }
}

// ---------------------------------------------------------------------------
extern "C" void kernel_launch(void* const* d_in, const int* in_sizes, int n_in,
                              void* d_out, int out_size)
{
    const float* x   = (const float*)d_in[0];
    const float* Wq  = (const float*)d_in[1];
    const float* Wk  = (const float*)d_in[2];
    const float* Wv  = (const float*)d_in[3];
    const float* Wo  = (const float*)d_in[4];
    const float* bo  = (const float*)d_in[5];
    const float* W1  = (const float*)d_in[6];
    const float* b1  = (const float*)d_in[7];
    const float* W2  = (const float*)d_in[8];
    const float* b2  = (const float*)d_in[9];
    const float* g1  = (const float*)d_in[10];
    const float* be1 = (const float*)d_in[11];
    const float* g2  = (const float*)d_in[12];
    const float* be2 = (const float*)d_in[13];
    float* out = (float*)d_out;

    float *x2;
    __half *h1, *qkv, *vt, *att, *h2, *mid;
    __half *wqkvT, *woT, *w1T, *w2T;
    cudaGetSymbolAddress((void**)&h1,   g_h1);
    cudaGetSymbolAddress((void**)&qkv,  g_qkv);
    cudaGetSymbolAddress((void**)&vt,   g_vt);
    cudaGetSymbolAddress((void**)&att,  g_att);
    cudaGetSymbolAddress((void**)&x2,   g_x2);
    cudaGetSymbolAddress((void**)&h2,   g_h2);
    cudaGetSymbolAddress((void**)&mid,  g_mid);
    cudaGetSymbolAddress((void**)&wqkvT, g_wqkvT);
    cudaGetSymbolAddress((void**)&woT,  g_woT);
    cudaGetSymbolAddress((void**)&w1T,  g_w1T);
    cudaGetSymbolAddress((void**)&w2T,  g_w2T);

    const int GSMEM = 2 * 8192 * 4;    // 64 KB
    cudaFuncSetAttribute(gemm_fp16<0>, cudaFuncAttributeMaxDynamicSharedMemorySize, GSMEM);
    cudaFuncSetAttribute(gemm_fp16<1>, cudaFuncAttributeMaxDynamicSharedMemorySize, GSMEM);
    cudaFuncSetAttribute(gemm_fp16<2>, cudaFuncAttributeMaxDynamicSharedMemorySize, GSMEM);

    dim3 blk(256);
    dim3 tblk(32, 8);

    // ---- ALL weight transposes in ONE launch (Wq scaled 2^-5 into fused wqkvT)
    transpose_weights<<<12288, tblk>>>(Wq, Wk, Wv, Wo, W1, W2,
                                       wqkvT, woT, w1T, w2T);

    // ---- LN1: x -> h1 (fp16)
    ln_kernel<<<ROWS, blk>>>(x, g1, be1, h1);

    // ---- fused QKV as ONE exact-size GEMM: qkv[4096][3072] = h1 @ wqkvT^T (fp16 out)
    gemm_fp16<0><<<dim3(NQKV / 128, ROWS / 128, 1), blk, GSMEM>>>(
        h1, wqkvT, nullptr, qkv, nullptr, nullptr,
        NQKV, Dn, Dn, Dn, NQKV);

    // ---- V transpose (fp16): qkv cols [2048 + h*64 ..] -> vt [z][HD][T]
    transpose_h<<<dim3(HDn / 32, Tn / 32, ZHD), tblk>>>(
        qkv + 2048, vt, NQKV,
        (long long)Tn * NQKV, Hn, (long long)HDn, Hn,
        Tn, (long long)HDn * Tn);

    // ---- flash attention (fp16) -> att (fp16, concat layout)
    flash_fp16<<<dim3(Tn / 128, ZHD), blk>>>(qkv, vt, att);

    // ---- O projection + bias + residual: x2 = x + att @ Wo + bo (fp32 out)
    gemm_fp16<2><<<dim3(Dn / 128, ROWS / 128, 1), blk, GSMEM>>>(
        att, woT, x2, nullptr, bo, x,
        Dn, Dn, Dn, Dn, Dn);

    // ---- LN2: x2 -> h2 (fp16)
    ln_kernel<<<ROWS, blk>>>(x2, g2, be2, h2);

    // ---- FFN1: mid = relu(h2 @ W1 + b1) (fp16 out)
    gemm_fp16<1><<<dim3(4 * Dn / 128, ROWS / 128, 1), blk, GSMEM>>>(
        h2, w1T, nullptr, mid, b1, nullptr,
        4 * Dn, Dn, Dn, Dn, 4 * Dn);

    // ---- FFN2: out = x2 + mid @ W2 + b2 (fp32 out)
    gemm_fp16<2><<<dim3(Dn / 128, ROWS / 128, 1), blk, GSMEM>>>(
        mid, w2T, out, nullptr, b2, x2,
        Dn, 4 * Dn, 4 * Dn, 4 * Dn, Dn);
}

// round 16
// speedup vs baseline: 1.0848x; 1.0188x over previous
#include <cuda_runtime.h>
#include <cuda_fp16.h>

// Problem constants
#define Tn   2048
#define Dn   1024
#define Hn   16
#define HDn  64
#define Bn   2
#define ROWS (Bn * Tn)   // 4096
#define ZHD  (Bn * Hn)   // 32
#define NQKV 3072        // q|k|v fused output width

// ---------------- scratch (static device globals; no allocations) ----------
__device__ __half g_h1 [ROWS * Dn];
__device__ __half g_qkv[ROWS * NQKV];            // [b*T][3072]: q|k|v (q pre-scaled via Wq)
__device__ __half g_att[ROWS * Dn];
__device__ float  g_x2 [ROWS * Dn];
__device__ __half g_h2 [ROWS * Dn];
__device__ __half g_mid[ROWS * 4 * Dn];
__device__ __half g_wqkvT[NQKV * Dn];            // [3072][1024] fused B operand
__device__ __half g_woT [Dn * Dn];
__device__ __half g_w1T [4 * Dn * Dn];           // [4D][D]
__device__ __half g_w2T [4 * Dn * Dn];           // [D][4D]

// ---------------------------------------------------------------------------
__device__ __forceinline__ unsigned smem_u32(const void* p) {
    return (unsigned)__cvta_generic_to_shared(p);
}
__device__ __forceinline__ void cp16(unsigned dst, const void* src) {
    asm volatile("cp.async.cg.shared.global [%0],[%1],16;\n" :: "r"(dst), "l"(src));
}
#define CP_COMMIT()  asm volatile("cp.async.commit_group;" ::: "memory")
#define CP_WAIT(n)   asm volatile("cp.async.wait_group %0;" :: "n"(n) : "memory")

#define MMA_FP16(d, a, b) \
    asm volatile("mma.sync.aligned.m16n8k16.row.col.f32.f16.f16.f32 " \
                 "{%0,%1,%2,%3},{%4,%5,%6,%7},{%8,%9},{%0,%1,%2,%3};\n" \
                 : "+f"((d)[0]), "+f"((d)[1]), "+f"((d)[2]), "+f"((d)[3]) \
                 : "r"((a)[0]), "r"((a)[1]), "r"((a)[2]), "r"((a)[3]), \
                   "r"((b)[0]), "r"((b)[1]))

// Warp-collective fragment loads: 4 x m8n8 b16 matrices (plain + transposing).
#define LDSM_X4(r0, r1, r2, r3, addr) \
    asm volatile("ldmatrix.sync.aligned.m8n8.x4.shared.b16 {%0,%1,%2,%3},[%4];\n" \
                 : "=r"(r0), "=r"(r1), "=r"(r2), "=r"(r3) : "r"(addr))
#define LDSM_X4_T(r0, r1, r2, r3, addr) \
    asm volatile("ldmatrix.sync.aligned.m8n8.x4.trans.shared.b16 {%0,%1,%2,%3},[%4];\n" \
                 : "=r"(r0), "=r"(r1), "=r"(r2), "=r"(r3) : "r"(addr))

__device__ __forceinline__ unsigned pack_h2(float a, float b) {
    __half2 h = __floats2half2_rn(a, b);
    return *reinterpret_cast<unsigned*>(&h);
}

// ---------------------------------------------------------------------------
// prep_kernel (ONE launch): blocks 0..12287 = weight transposes fp32->fp16
// (Wq/Wk/Wv -> fused wqkvT with Wq scaled 2^-5, Wo, W1, W2);
// blocks 12288..16383 = LN1 rows (x -> h1 fp16).
// ---------------------------------------------------------------------------
__global__ void prep_kernel(const float* __restrict__ Wq,
                            const float* __restrict__ Wk,
                            const float* __restrict__ Wv,
                            const float* __restrict__ Wo,
                            const float* __restrict__ W1,
                            const float* __restrict__ W2,
                            __half* __restrict__ wqkvT,
                            __half* __restrict__ woT,
                            __half* __restrict__ w1T,
                            __half* __restrict__ w2T,
                            const float* __restrict__ x,
                            const float* __restrict__ g1,
                            const float* __restrict__ be1,
                            __half* __restrict__ h1)
{
    const int tb = blockIdx.x;
    const int tx = threadIdx.x, ty = threadIdx.y;

    if (tb >= 12288) {
        // ---- LayerNorm row
        const long long row = tb - 12288;
        const int tid = ty * 32 + tx;
        const float* xr = x + row * Dn;

        float v[4];
        float s = 0.f;
#pragma unroll
        for (int i = 0; i < 4; i++) { v[i] = xr[tid + 256 * i]; s += v[i]; }

        __shared__ float red[8];
        __shared__ float sh_mu, sh_rstd;

#pragma unroll
        for (int o = 16; o > 0; o >>= 1) s += __shfl_xor_sync(0xffffffffu, s, o);
        if ((tid & 31) == 0) red[tid >> 5] = s;
        __syncthreads();
        if (tid == 0) {
            float t = 0.f;
            for (int i = 0; i < 8; i++) t += red[i];
            sh_mu = t * (1.0f / Dn);
        }
        __syncthreads();
        float mu = sh_mu;

        float ss = 0.f;
#pragma unroll
        for (int i = 0; i < 4; i++) { float d = v[i] - mu; ss += d * d; }
#pragma unroll
        for (int o = 16; o > 0; o >>= 1) ss += __shfl_xor_sync(0xffffffffu, ss, o);
        if ((tid & 31) == 0) red[tid >> 5] = ss;
        __syncthreads();
        if (tid == 0) {
            float t = 0.f;
            for (int i = 0; i < 8; i++) t += red[i];
            sh_rstd = rsqrtf(t * (1.0f / Dn) + 1e-5f);
        }
        __syncthreads();
        float rstd = sh_rstd;

#pragma unroll
        for (int i = 0; i < 4; i++) {
            int c = tid + 256 * i;
            h1[row * Dn + c] = __float2half_rn((v[i] - mu) * rstd * g1[c] + be1[c]);
        }
        return;
    }

    // ---- weight transpose tile
    __shared__ float t[32][33];
    const float* in;
    __half* outp;
    int ldin, ldout, cx, cy;
    float scale = 1.0f;

    if (tb < 3072) {
        const int seg = tb / 1024;
        const int r   = tb % 1024;
        const int z   = r / 64;            // head
        const int rr  = r % 64;
        cx = rr & 1;                       // HD tiles: 2
        cy = rr >> 1;                      // D tiles: 32
        const float* W = (seg == 0) ? Wq : (seg == 1) ? Wk : Wv;
        in   = W + (long long)z * Dn * HDn;
        ldin = HDn;
        outp  = wqkvT + (long long)seg * Dn * Dn + (long long)z * HDn * Dn;
        ldout = Dn;
        if (seg == 0) scale = 0.03125f;    // fold attention scale into Wq
    } else if (tb < 4096) {
        const int r = tb - 3072;
        cx = r & 31; cy = r >> 5;          // [D][D]
        in = Wo; ldin = Dn; outp = woT; ldout = Dn;
    } else if (tb < 8192) {
        const int r = tb - 4096;
        cx = r & 127; cy = r >> 7;         // [D][4D]
        in = W1; ldin = 4 * Dn; outp = w1T; ldout = Dn;
    } else {
        const int r = tb - 8192;
        cx = r & 31; cy = r >> 5;          // [4D][D]
        in = W2; ldin = Dn; outp = w2T; ldout = 4 * Dn;
    }

    const int c0 = cx * 32, r0 = cy * 32;
#pragma unroll
    for (int i = 0; i < 32; i += 8)
        t[ty + i][tx] = in[(long long)(r0 + ty + i) * ldin + c0 + tx];
    __syncthreads();
#pragma unroll
    for (int i = 0; i < 32; i += 8)
        outp[(long long)(c0 + ty + i) * ldout + r0 + tx] =
            __float2half_rn(t[tx][ty + i] * scale);
}

// ---------------------------------------------------------------------------
// gemm_fp16: single-pass FP16 GEMM (fp32 accum), ldmatrix fragment loads.
// (unchanged from R12/R14 winner)
// ---------------------------------------------------------------------------
template <int EPI>
__launch_bounds__(256, 2)
__global__ void gemm_fp16(const __half* __restrict__ A,
                          const __half* __restrict__ B,
                          float* __restrict__ C,
                          __half* __restrict__ Ch,
                          const float* __restrict__ bias,
                          const float* __restrict__ res,
                          int N, int K, int lda, int ldb, int ldc)
{
    extern __shared__ unsigned sm[];   // stage s: A at s*8192 words, B at +4096 words

    const int m0 = blockIdx.y * 128;
    const int n0 = blockIdx.x * 128;

    const int tid  = threadIdx.x;
    const int lane = tid & 31;
    const int w    = tid >> 5;
    const int wm   = (w & 1) * 64;
    const int wn   = (w >> 1) * 32;
    const int q    = lane >> 2;
    const int kb   = lane & 3;
    const int nk   = K / 64;

    const int mi = lane >> 3;
    const int ri = lane & 7;
    const unsigned aRow = wm + (mi & 1) * 8 + ri;
    const unsigned bRow = wn + (mi >> 1) * 8 + ri;
    const int caA = mi >> 1;
    const int caB = mi & 1;

    const int lrow = tid >> 3;
    const int lg   = tid & 7;
    const unsigned lsw = ((unsigned)(lg * 4)) ^ ((unsigned)((lrow & 7) * 4));

    float acc[4][4][4];
#pragma unroll
    for (int mt = 0; mt < 4; mt++)
#pragma unroll
        for (int nt = 0; nt < 4; nt++)
#pragma unroll
            for (int j = 0; j < 4; j++) acc[mt][nt][j] = 0.f;

    auto load_stage = [&](int st, int kt) {
        unsigned* sb = sm + st * 8192;
        const int k0 = kt * 64;
#pragma unroll
        for (int i = 0; i < 4; i++) {
            int row = lrow + 32 * i;
            unsigned off = row * 32 + lsw;
            cp16(smem_u32(sb + off),        A + (long long)(m0 + row) * lda + k0 + lg * 8);
            cp16(smem_u32(sb + 4096 + off), B + (long long)(n0 + row) * ldb + k0 + lg * 8);
        }
        CP_COMMIT();
    };

    load_stage(0, 0);

    const unsigned sbase0 = smem_u32(sm);

    for (int kt = 0; kt < nk; kt++) {
        if (kt + 1 < nk) {
            load_stage((kt + 1) & 1, kt + 1);
            CP_WAIT(1);
        } else {
            CP_WAIT(0);
        }
        __syncthreads();

        const unsigned sA = sbase0 + (kt & 1) * 32768;
        const unsigned sB = sA + 16384;
#pragma unroll
        for (int c = 0; c < 4; c++) {
            unsigned a[4][4], b[4][2];
            const unsigned swzA = (unsigned)(((2 * c + caA) ^ ri) << 4);
            const unsigned swzB = (unsigned)(((2 * c + caB) ^ ri) << 4);
#pragma unroll
            for (int mt = 0; mt < 4; mt++) {
                unsigned addr = sA + (aRow + mt * 16) * 128 + swzA;
                LDSM_X4(a[mt][0], a[mt][1], a[mt][2], a[mt][3], addr);
            }
#pragma unroll
            for (int p = 0; p < 2; p++) {
                unsigned addr = sB + (bRow + p * 16) * 128 + swzB;
                LDSM_X4(b[2 * p][0], b[2 * p][1], b[2 * p + 1][0], b[2 * p + 1][1], addr);
            }
#pragma unroll
            for (int mt = 0; mt < 4; mt++)
#pragma unroll
                for (int nt = 0; nt < 4; nt++)
                    MMA_FP16(acc[mt][nt], a[mt], b[nt]);
        }
        __syncthreads();
    }

#pragma unroll
    for (int mt = 0; mt < 4; mt++)
#pragma unroll
        for (int nt = 0; nt < 4; nt++) {
            const float* a4 = acc[mt][nt];
            const long long r0 = m0 + wm + mt * 16 + q;
            const long long r1 = r0 + 8;
            const int cc = n0 + wn + nt * 8 + kb * 2;
            if (EPI == 0) {
                *reinterpret_cast<unsigned*>(&Ch[r0 * ldc + cc]) = pack_h2(a4[0], a4[1]);
                *reinterpret_cast<unsigned*>(&Ch[r1 * ldc + cc]) = pack_h2(a4[2], a4[3]);
            } else if (EPI == 1) {
                float2 bv = *reinterpret_cast<const float2*>(&bias[cc]);
                *reinterpret_cast<unsigned*>(&Ch[r0 * ldc + cc]) =
                    pack_h2(fmaxf(a4[0] + bv.x, 0.f), fmaxf(a4[1] + bv.y, 0.f));
                *reinterpret_cast<unsigned*>(&Ch[r1 * ldc + cc]) =
                    pack_h2(fmaxf(a4[2] + bv.x, 0.f), fmaxf(a4[3] + bv.y, 0.f));
            } else {
                float2 bv = *reinterpret_cast<const float2*>(&bias[cc]);
                float2 q0 = *reinterpret_cast<const float2*>(&res[r0 * ldc + cc]);
                float2 q1 = *reinterpret_cast<const float2*>(&res[r1 * ldc + cc]);
                *reinterpret_cast<float2*>(&C[r0 * ldc + cc]) =
                    make_float2(a4[0] + bv.x + q0.x, a4[1] + bv.y + q0.y);
                *reinterpret_cast<float2*>(&C[r1 * ldc + cc]) =
                    make_float2(a4[2] + bv.x + q1.x, a4[3] + bv.y + q1.y);
            }
        }
}

// ---------------------------------------------------------------------------
// Flash attention, FP16/fp32. V read DIRECTLY from qkv [token][hd]; PV
// B-fragments produced by ldmatrix.trans (bitwise == old vt path).
// grid = (Tn/128, ZHD), block = 256.
// Static smem: 8192 words = 32 KB (Q 0..4095, K 4096..6143, V 6144..8191).
// ---------------------------------------------------------------------------
__launch_bounds__(256)
__global__ void flash_fp16(const __half* __restrict__ qkv,
                           __half* __restrict__ att)
{
    __shared__ __align__(16) unsigned s_w[8192];

    const int z  = blockIdx.y;
    const int m0 = blockIdx.x * 128;
    const int tid = threadIdx.x, lane = tid & 31, w = tid >> 5;
    const int q  = lane >> 2;
    const int kb = lane & 3;
    const unsigned qx = (unsigned)(q << 2);

    // ldmatrix lane mappings
    const int mi = lane >> 3;
    const int ri = lane & 7;
    const unsigned bRow = (unsigned)((mi >> 1) * 8 + ri);   // K frags (non-trans)
    const int caB = mi & 1;
    const unsigned vRowOff = (unsigned)((mi & 1) * 8 + ri) * 128;  // V frags (trans)
    const int vch = mi >> 1;

    const long long bbase = (long long)(z >> 4) * Tn * NQKV;   // batch row base
    const int hcol = (z & 15) * HDn;                           // head column

    // ---- stage Q (128x64 halfs, swizzled), extract fp16 A-fragments
    unsigned qf[4][4];
    {
        const __half* Qg = qkv + bbase + (long long)m0 * NQKV + hcol;
#pragma unroll
        for (int i = 0; i < 4; i++) {
            int idx = tid + 256 * i;
            int r = idx >> 3, ch = idx & 7;
            unsigned sw = r * 32 + (((unsigned)(ch * 4)) ^ ((unsigned)((r & 7) * 4)));
            cp16(smem_u32(s_w + sw), Qg + (long long)r * NQKV + ch * 8);
        }
        CP_COMMIT();
        CP_WAIT(0);
        __syncthreads();
        const int ra = w * 16 + q;
#pragma unroll
        for (int c = 0; c < 4; c++) {
            const unsigned g0 = ((unsigned)(c * 8) ^ qx) + kb;
            const unsigned g1 = ((unsigned)(c * 8 + 4) ^ qx) + kb;
            qf[c][0] = s_w[ra * 32 + g0];
            qf[c][1] = s_w[(ra + 8) * 32 + g0];
            qf[c][2] = s_w[ra * 32 + g1];
            qf[c][3] = s_w[(ra + 8) * 32 + g1];
        }
        __syncthreads();
    }

    float m0s = -1e30f, m1s = -1e30f;
    float l0 = 0.f, l1 = 0.f;
    float acc_o[8][4];
#pragma unroll
    for (int nt = 0; nt < 8; nt++)
#pragma unroll
        for (int j = 0; j < 4; j++) acc_o[nt][j] = 0.f;

    const int nkb = blockIdx.x * 2 + 2;
    const __half* Kg = qkv + bbase + 1024 + hcol;
    const __half* Vg = qkv + bbase + 2048 + hcol;
    const int rga = m0 + w * 16 + q;
    const int rgb = rga + 8;

    const unsigned kBase = smem_u32(s_w) + 16384;   // K tile byte base
    const unsigned vBase = smem_u32(s_w) + 24576;   // V tile byte base

    for (int it = 0; it < nkb; it++) {
        // ---- load K (64x64) and V (64 tokens x 64 hd) fp16 tiles, swizzled
        {
#pragma unroll
            for (int i = 0; i < 2; i++) {
                int idx = tid + 256 * i;
                int r = idx >> 3, ch = idx & 7;
                unsigned sw = r * 32 + (((unsigned)(ch * 4)) ^ ((unsigned)((r & 7) * 4)));
                const long long grow = (long long)(it * 64 + r) * NQKV + ch * 8;
                cp16(smem_u32(s_w + 4096 + sw), Kg + grow);
                cp16(smem_u32(s_w + 6144 + sw), Vg + grow);
            }
            CP_COMMIT();
            CP_WAIT(0);
        }
        __syncthreads();

        // ---- S = Q K^T (fp16, fp32 accum); K frags via ldmatrix
        float s[8][4];
#pragma unroll
        for (int nt = 0; nt < 8; nt++)
#pragma unroll
            for (int j = 0; j < 4; j++) s[nt][j] = 0.f;

#pragma unroll
        for (int c = 0; c < 4; c++) {
            unsigned bbf[8][2];
            const unsigned swzB = (unsigned)(((2 * c + caB) ^ ri) << 4);
#pragma unroll
            for (int p = 0; p < 4; p++) {
                unsigned addr = kBase + (bRow + p * 16) * 128 + swzB;
                LDSM_X4(bbf[2 * p][0], bbf[2 * p][1],
                        bbf[2 * p + 1][0], bbf[2 * p + 1][1], addr);
            }
#pragma unroll
            for (int nt = 0; nt < 8; nt++)
                MMA_FP16(s[nt], qf[c], bbf[nt]);
        }

        // ---- causal mask
        const int cb = kb * 2;
        if (it * 64 + 63 > rga) {
#pragma unroll
            for (int nt = 0; nt < 8; nt++) {
                int cg = it * 64 + nt * 8 + cb;
                if (cg > rga)     s[nt][0] = -1e30f;
                if (cg + 1 > rga) s[nt][1] = -1e30f;
                if (cg > rgb)     s[nt][2] = -1e30f;
                if (cg + 1 > rgb) s[nt][3] = -1e30f;
            }
        }

        // ---- online softmax (fp32)
        float ml0 = -1e30f, ml1 = -1e30f;
#pragma unroll
        for (int nt = 0; nt < 8; nt++) {
            ml0 = fmaxf(ml0, fmaxf(s[nt][0], s[nt][1]));
            ml1 = fmaxf(ml1, fmaxf(s[nt][2], s[nt][3]));
        }
        ml0 = fmaxf(ml0, __shfl_xor_sync(0xffffffffu, ml0, 1));
        ml0 = fmaxf(ml0, __shfl_xor_sync(0xffffffffu, ml0, 2));
        ml1 = fmaxf(ml1, __shfl_xor_sync(0xffffffffu, ml1, 1));
        ml1 = fmaxf(ml1, __shfl_xor_sync(0xffffffffu, ml1, 2));
        float mn0 = fmaxf(m0s, ml0), mn1 = fmaxf(m1s, ml1);
        float al0 = __expf(m0s - mn0), al1 = __expf(m1s - mn1);
        m0s = mn0; m1s = mn1;

        float rs0 = 0.f, rs1 = 0.f;
#pragma unroll
        for (int nt = 0; nt < 8; nt++) {
            s[nt][0] = __expf(s[nt][0] - mn0);
            s[nt][1] = __expf(s[nt][1] - mn0);
            s[nt][2] = __expf(s[nt][2] - mn1);
            s[nt][3] = __expf(s[nt][3] - mn1);
            rs0 += s[nt][0] + s[nt][1];
            rs1 += s[nt][2] + s[nt][3];
        }
        rs0 += __shfl_xor_sync(0xffffffffu, rs0, 1);
        rs0 += __shfl_xor_sync(0xffffffffu, rs0, 2);
        rs1 += __shfl_xor_sync(0xffffffffu, rs1, 1);
        rs1 += __shfl_xor_sync(0xffffffffu, rs1, 2);
        l0 = l0 * al0 + rs0;
        l1 = l1 * al1 + rs1;
#pragma unroll
        for (int nt = 0; nt < 8; nt++) {
            acc_o[nt][0] *= al0; acc_o[nt][1] *= al0;
            acc_o[nt][2] *= al1; acc_o[nt][3] *= al1;
        }

        // ---- P C-frag -> fp16 A-frags (k16 identity) and PV;
        //      V frags via ldmatrix.TRANS on [token][hd] tile
#pragma unroll
        for (int c = 0; c < 4; c++) {
            unsigned pa[4];
            pa[0] = pack_h2(s[2 * c][0],     s[2 * c][1]);
            pa[1] = pack_h2(s[2 * c][2],     s[2 * c][3]);
            pa[2] = pack_h2(s[2 * c + 1][0], s[2 * c + 1][1]);
            pa[3] = pack_h2(s[2 * c + 1][2], s[2 * c + 1][3]);
            unsigned bbf[8][2];
            const unsigned rowAddr = vBase + (unsigned)(c * 16) * 128 + vRowOff;
#pragma unroll
            for (int p = 0; p < 4; p++) {
                unsigned addr = rowAddr + ((((unsigned)(2 * p + vch)) ^ ri) << 4);
                LDSM_X4_T(bbf[2 * p][0], bbf[2 * p][1],
                          bbf[2 * p + 1][0], bbf[2 * p + 1][1], addr);
            }
#pragma unroll
            for (int nt = 0; nt < 8; nt++)
                MMA_FP16(acc_o[nt], pa, bbf[nt]);
        }
        __syncthreads();     // protect smem before next tile's cp.async
    }

    // ---- epilogue: normalize, write fp16 concat layout [b][t][h*64+e]
    const float i0 = 1.f / l0, i1 = 1.f / l1;
    __half* op = att + (long long)(z >> 4) * Tn * Dn + (z & 15) * HDn;
    const int cb = kb * 2;
#pragma unroll
    for (int nt = 0; nt < 8; nt++) {
        *reinterpret_cast<unsigned*>(op + (long long)rga * Dn + nt * 8 + cb) =
            pack_h2(acc_o[nt][0] * i0, acc_o[nt][1] * i0);
        *reinterpret_cast<unsigned*>(op + (long long)rgb * Dn + nt * 8 + cb) =
            pack_h2(acc_o[nt][2] * i1, acc_o[nt][3] * i1);
    }
}

// ---------------------------------------------------------------------------
// LayerNorm over last dim (1024), output fp16. (used for LN2 only)
// ---------------------------------------------------------------------------
__launch_bounds__(256)
__global__ void ln_kernel(const float* __restrict__ x,
                          const float* __restrict__ g,
                          const float* __restrict__ be,
                          __half* __restrict__ outp)
{
    long long row = blockIdx.x;
    const float* xr = x + row * Dn;
    int tid = threadIdx.x;

    float v[4];
    float s = 0.f;
#pragma unroll
    for (int i = 0; i < 4; i++) { v[i] = xr[tid + 256 * i]; s += v[i]; }

    __shared__ float red[8];
    __shared__ float sh_mu, sh_rstd;

#pragma unroll
    for (int o = 16; o > 0; o >>= 1) s += __shfl_xor_sync(0xffffffffu, s, o);
    if ((tid & 31) == 0) red[tid >> 5] = s;
    __syncthreads();
    if (tid == 0) {
        float t = 0.f;
        for (int i = 0; i < 8; i++) t += red[i];
        sh_mu = t * (1.0f / Dn);
    }
    __syncthreads();
    float mu = sh_mu;

    float ss = 0.f;
#pragma unroll
    for (int i = 0; i < 4; i++) { float d = v[i] - mu; ss += d * d; }
#pragma unroll
    for (int o = 16; o > 0; o >>= 1) ss += __shfl_xor_sync(0xffffffffu, ss, o);
    if ((tid & 31) == 0) red[tid >> 5] = ss;
    __syncthreads();
    if (tid == 0) {
        float t = 0.f;
        for (int i = 0; i < 8; i++) t += red[i];
        sh_rstd = rsqrtf(t * (1.0f / Dn) + 1e-5f);
    }
    __syncthreads();
    float rstd = sh_rstd;

#pragma unroll
    for (int i = 0; i < 4; i++) {
        int c = tid + 256 * i;
        outp[row * Dn + c] = __float2half_rn((v[i] - mu) * rstd * g[c] + be[c]);
    }
}

// ---------------------------------------------------------------------------
extern "C" void kernel_launch(void* const* d_in, const int* in_sizes, int n_in,
                              void* d_out, int out_size)
{
    const float* x   = (const float*)d_in[0];
    const float* Wq  = (const float*)d_in[1];
    const float* Wk  = (const float*)d_in[2];
    const float* Wv  = (const float*)d_in[3];
    const float* Wo  = (const float*)d_in[4];
    const float* bo  = (const float*)d_in[5];
    const float* W1  = (const float*)d_in[6];
    const float* b1  = (const float*)d_in[7];
    const float* W2  = (const float*)d_in[8];
    const float* b2  = (const float*)d_in[9];
    const float* g1  = (const float*)d_in[10];
    const float* be1 = (const float*)d_in[11];
    const float* g2  = (const float*)d_in[12];
    const float* be2 = (const float*)d_in[13];
    float* out = (float*)d_out;

    float *x2;
    __half *h1, *qkv, *att, *h2, *mid;
    __half *wqkvT, *woT, *w1T, *w2T;
    cudaGetSymbolAddress((void**)&h1,   g_h1);
    cudaGetSymbolAddress((void**)&qkv,  g_qkv);
    cudaGetSymbolAddress((void**)&att,  g_att);
    cudaGetSymbolAddress((void**)&x2,   g_x2);
    cudaGetSymbolAddress((void**)&h2,   g_h2);
    cudaGetSymbolAddress((void**)&mid,  g_mid);
    cudaGetSymbolAddress((void**)&wqkvT, g_wqkvT);
    cudaGetSymbolAddress((void**)&woT,  g_woT);
    cudaGetSymbolAddress((void**)&w1T,  g_w1T);
    cudaGetSymbolAddress((void**)&w2T,  g_w2T);

    const int GSMEM = 2 * 8192 * 4;    // 64 KB
    cudaFuncSetAttribute(gemm_fp16<0>, cudaFuncAttributeMaxDynamicSharedMemorySize, GSMEM);
    cudaFuncSetAttribute(gemm_fp16<1>, cudaFuncAttributeMaxDynamicSharedMemorySize, GSMEM);
    cudaFuncSetAttribute(gemm_fp16<2>, cudaFuncAttributeMaxDynamicSharedMemorySize, GSMEM);

    dim3 blk(256);
    dim3 tblk(32, 8);

    // ---- prep: ALL weight transposes + LN1 in ONE launch
    prep_kernel<<<12288 + ROWS, tblk>>>(Wq, Wk, Wv, Wo, W1, W2,
                                        wqkvT, woT, w1T, w2T,
                                        x, g1, be1, h1);

    // ---- fused QKV as ONE exact-size GEMM: qkv[4096][3072] = h1 @ wqkvT^T (fp16 out)
    gemm_fp16<0><<<dim3(NQKV / 128, ROWS / 128, 1), blk, GSMEM>>>(
        h1, wqkvT, nullptr, qkv, nullptr, nullptr,
        NQKV, Dn, Dn, Dn, NQKV);

    // ---- flash attention (fp16) -> att; V consumed in-place via ldmatrix.trans
    flash_fp16<<<dim3(Tn / 128, ZHD), blk>>>(qkv, att);

    // ---- O projection + bias + residual: x2 = x + att @ Wo + bo (fp32 out)
    gemm_fp16<2><<<dim3(Dn / 128, ROWS / 128, 1), blk, GSMEM>>>(
        att, woT, x2, nullptr, bo, x,
        Dn, Dn, Dn, Dn, Dn);

    // ---- LN2: x2 -> h2 (fp16)
    ln_kernel<<<ROWS, blk>>>(x2, g2, be2, h2);

    // ---- FFN1: mid = relu(h2 @ W1 + b1) (fp16 out)
    gemm_fp16<1><<<dim3(4 * Dn / 128, ROWS / 128, 1), blk, GSMEM>>>(
        h2, w1T, nullptr, mid, b1, nullptr,
        4 * Dn, Dn, Dn, Dn, 4 * Dn);

    // ---- FFN2: out = x2 + mid @ W2 + b2 (fp32 out)
    gemm_fp16<2><<<dim3(Dn / 128, ROWS / 128, 1), blk, GSMEM>>>(
        mid, w2T, out, nullptr, b2, x2,
        Dn, 4 * Dn, 4 * Dn, 4 * Dn, Dn);
}